// round 7
// baseline (speedup 1.0000x reference)
#include <cuda_runtime.h>
#include <cuda_fp16.h>
#include <math.h>
#include <stdint.h>

#define DIMD  1024
#define ADIMD 256
#define HIDD  4096
#define NTOK  4096
#define NB    4
#define MROWS (NB * NTOK)        // 16384
#define DEPTH 4
#define SCALE_A 0.25f

// ---------------- scratch (device globals) ----------------
__device__ __half g_h  [(size_t)MROWS * DIMD];
__device__ __half g_q  [(size_t)MROWS * ADIMD];
__device__ __half g_k  [(size_t)MROWS * ADIMD];
__device__ __half g_att[(size_t)MROWS * ADIMD];
__device__ __half g_hid[(size_t)MROWS * HIDD];
__device__ float  g_a  [MROWS];
__device__ float  g_rn [NB];
__device__ float  g_G  [NB * ADIMD];
__device__ float  g_Gp [NB * 32 * ADIMD];
__device__ __half g_Wqt[(size_t)DEPTH * ADIMD * DIMD];
__device__ __half g_Wkt[(size_t)DEPTH * ADIMD * DIMD];
__device__ __half g_Wpt[(size_t)DEPTH * ADIMD * ADIMD];
__device__ __half g_Wft[(size_t)DEPTH * DIMD * ADIMD];
__device__ __half g_W1t[(size_t)DEPTH * HIDD * DIMD];
__device__ __half g_W2t[(size_t)DEPTH * DIMD * HIDD];

// ---------------- helpers ----------------
__device__ __forceinline__ float warpSum(float v) {
#pragma unroll
    for (int o = 16; o > 0; o >>= 1) v += __shfl_xor_sync(0xFFFFFFFFu, v, o);
    return v;
}
__device__ __forceinline__ uint32_t smem_u32(const void* p) {
    uint32_t a;
    asm("{ .reg .u64 t; cvta.to.shared.u64 t, %1; cvt.u32.u64 %0, t; }" : "=r"(a) : "l"(p));
    return a;
}
__device__ __forceinline__ void cp_async16(uint32_t saddr, const void* g) {
    asm volatile("cp.async.cg.shared.global [%0], [%1], 16;" :: "r"(saddr), "l"(g));
}
__device__ __forceinline__ void cp_commit() { asm volatile("cp.async.commit_group;"); }
template <int N> __device__ __forceinline__ void cp_wait() {
    asm volatile("cp.async.wait_group %0;" :: "n"(N));
}
__device__ __forceinline__ void ldsm4(uint32_t& r0, uint32_t& r1, uint32_t& r2, uint32_t& r3,
                                      uint32_t addr) {
    asm volatile("ldmatrix.sync.aligned.m8n8.x4.shared.b16 {%0,%1,%2,%3}, [%4];"
                 : "=r"(r0), "=r"(r1), "=r"(r2), "=r"(r3) : "r"(addr));
}
__device__ __forceinline__ void mma_f16(float& c0, float& c1, float& c2, float& c3,
                                        uint32_t a0, uint32_t a1, uint32_t a2, uint32_t a3,
                                        uint32_t b0, uint32_t b1) {
    asm volatile(
        "mma.sync.aligned.m16n8k16.row.col.f32.f16.f16.f32 "
        "{%0,%1,%2,%3}, {%4,%5,%6,%7}, {%8,%9}, {%0,%1,%2,%3};"
        : "+f"(c0), "+f"(c1), "+f"(c2), "+f"(c3)
        : "r"(a0), "r"(a1), "r"(a2), "r"(a3), "r"(b0), "r"(b1));
}

// ======== fp16 pipelined GEMM: CTA 128x256x32, warps 2x4 of 64x64 ==========
#define A_BYTES     10240                 // 128 rows x 40 halfs (80B)
#define B_BYTES     20480                 // 256 rows x 40 halfs
#define STAGE_BYTES (A_BYTES + B_BYTES)   // 30720
#define NSTAGE      3
#define SMEM_HGEMM  (NSTAGE * STAGE_BYTES)  // 92160

// EPI: 0 = half(AB+bias) | 1 = Cf32 += AB+bias | 2 = half(gelu(AB+bias))
//      3 = half(AB+bias+D)
template <int EPI>
__global__ __launch_bounds__(256)
void hgemm(int N, int K,
           const __half* __restrict__ A,     // [M][K]
           const __half* __restrict__ Bt,    // [N][K]
           const float* __restrict__ bias,   // [N]
           const __half* __restrict__ Dadd,  // [M][N] (EPI 3)
           void* __restrict__ Cv) {
    extern __shared__ char smraw[];
    const uint32_t sbase = smem_u32(smraw);

    const int bx = blockIdx.x, by = blockIdx.y;
    const int tid = threadIdx.x;
    const int lane = tid & 31;
    const int warp = tid >> 5;
    const int warpM = warp & 1;         // 2 warps over M (64 rows each)
    const int warpN = warp >> 1;        // 4 warps over N (64 cols each)
    const int tg  = lane & 3;

    const __half* Ab = A  + (size_t)by * 128 * K;
    const __half* Bb = Bt + (size_t)bx * 256 * K;

    // ldmatrix per-lane bases (same addressing scheme as validated 64x32 kernel)
    const uint32_t a_lane = (uint32_t)((warpM * 64 + (lane & 15)) * 80 + (lane >> 4) * 16);
    const uint32_t b_lane = (uint32_t)(A_BYTES +
        (warpN * 64 + (lane & 7) + 8 * (lane >> 4)) * 80 + ((lane >> 3) & 1) * 16);

    float acc[4][8][4];
#pragma unroll
    for (int mi = 0; mi < 4; mi++)
#pragma unroll
        for (int ni = 0; ni < 8; ni++)
#pragma unroll
            for (int r = 0; r < 4; r++) acc[mi][ni][r] = 0.f;

    const int T = K / 32;

    // A: 512 16B-chunks (2/thread). B: 1024 chunks (4/thread).
#define LOAD_TILE(t_, s_) do {                                                  \
        uint32_t _sa = sbase + (s_) * STAGE_BYTES;                              \
        uint32_t _sb = _sa + A_BYTES;                                           \
        const __half* _ga = Ab + (size_t)(t_) * 32;                            \
        const __half* _gb = Bb + (size_t)(t_) * 32;                            \
        _Pragma("unroll")                                                       \
        for (int _i = 0; _i < 2; _i++) {                                        \
            int _id = tid + _i * 256;                                           \
            int _r = _id >> 2, _c = _id & 3;                                    \
            cp_async16(_sa + _r * 80 + _c * 16, _ga + (size_t)_r * K + _c * 8); \
        }                                                                       \
        _Pragma("unroll")                                                       \
        for (int _i = 0; _i < 4; _i++) {                                        \
            int _id = tid + _i * 256;                                           \
            int _r = _id >> 2, _c = _id & 3;                                    \
            cp_async16(_sb + _r * 80 + _c * 16, _gb + (size_t)_r * K + _c * 8); \
        }                                                                       \
        cp_commit();                                                            \
    } while (0)

    LOAD_TILE(0, 0);
    if (T > 1) LOAD_TILE(1, 1);
    else cp_commit();

    for (int t = 0; t < T; t++) {
        cp_wait<1>();
        __syncthreads();
        if (t + 2 < T) LOAD_TILE(t + 2, (t + 2) % NSTAGE);
        else cp_commit();

        const uint32_t st = sbase + (t % NSTAGE) * STAGE_BYTES;
        const uint32_t a0addr = st + a_lane;
        const uint32_t b0addr = st + b_lane;
#pragma unroll
        for (int ks = 0; ks < 2; ks++) {
            uint32_t af[4][4];
#pragma unroll
            for (int mi = 0; mi < 4; mi++)
                ldsm4(af[mi][0], af[mi][1], af[mi][2], af[mi][3],
                      a0addr + mi * 1280 + ks * 32);
#pragma unroll
            for (int p = 0; p < 4; p++) {
                uint32_t b0, b1, b2, b3;
                ldsm4(b0, b1, b2, b3, b0addr + p * 1280 + ks * 32);
#pragma unroll
                for (int mi = 0; mi < 4; mi++) {
                    mma_f16(acc[mi][2*p][0], acc[mi][2*p][1],
                            acc[mi][2*p][2], acc[mi][2*p][3],
                            af[mi][0], af[mi][1], af[mi][2], af[mi][3], b0, b1);
                    mma_f16(acc[mi][2*p+1][0], acc[mi][2*p+1][1],
                            acc[mi][2*p+1][2], acc[mi][2*p+1][3],
                            af[mi][0], af[mi][1], af[mi][2], af[mi][3], b2, b3);
                }
            }
        }
        __syncthreads();
    }

    // epilogue
    const int grp8 = lane >> 2;
#pragma unroll
    for (int mi = 0; mi < 4; mi++) {
#pragma unroll
        for (int ni = 0; ni < 8; ni++) {
            int col = bx * 256 + warpN * 64 + ni * 8 + 2 * tg;
            int row0 = by * 128 + warpM * 64 + mi * 16 + grp8;
            float bv0 = bias[col], bv1 = bias[col + 1];
#pragma unroll
            for (int hh = 0; hh < 2; hh++) {
                int row = row0 + hh * 8;
                float v0 = acc[mi][ni][hh * 2 + 0] + bv0;
                float v1 = acc[mi][ni][hh * 2 + 1] + bv1;
                if (EPI == 1) {
                    float* Cp = (float*)Cv + (size_t)row * N + col;
                    float2 old = *(const float2*)Cp;
                    *(float2*)Cp = make_float2(v0 + old.x, v1 + old.y);
                } else {
                    __half* Cp = (__half*)Cv + (size_t)row * N + col;
                    if (EPI == 2) {
                        v0 = 0.5f * v0 * (1.0f + erff(v0 * 0.70710678118654752f));
                        v1 = 0.5f * v1 * (1.0f + erff(v1 * 0.70710678118654752f));
                    }
                    if (EPI == 3) {
                        float2 dv = __half22float2(
                            *(const __half2*)(Dadd + (size_t)row * N + col));
                        v0 += dv.x; v1 += dv.y;
                    }
                    *(__half2*)Cp = __floats2half2_rn(v0, v1);
                }
            }
        }
    }
}

// ---------------- weight transpose to fp16: W[K][N] -> Wt[N][K] ------------
__global__ void transpose_half(const float* __restrict__ W, __half* __restrict__ Wt,
                               int K, int N) {
    __shared__ float t[32][33];
    int n0 = blockIdx.x * 32, k0 = blockIdx.y * 32;
    int tx = threadIdx.x, ty = threadIdx.y;     // 32 x 8
#pragma unroll
    for (int i = 0; i < 4; i++)
        t[ty + 8 * i][tx] = W[(size_t)(k0 + ty + 8 * i) * N + n0 + tx];
    __syncthreads();
#pragma unroll
    for (int i = 0; i < 4; i++)
        Wt[(size_t)(n0 + ty + 8 * i) * K + k0 + tx] = __float2half(t[tx][ty + 8 * i]);
}

// ---------------- LayerNorm (fp32 in, fp16 out) ---------------------------
__global__ void ln_kernel(const float* __restrict__ x,
                          const float* __restrict__ g,
                          const float* __restrict__ b,
                          __half* __restrict__ out) {
    int row = blockIdx.x;
    const float* xr = x + (size_t)row * DIMD;
    float v[4];
    float s = 0.f, s2 = 0.f;
#pragma unroll
    for (int j = 0; j < 4; j++) {
        v[j] = xr[threadIdx.x + 256 * j];
        s += v[j]; s2 += v[j] * v[j];
    }
    __shared__ float sh[2][8];
    s = warpSum(s); s2 = warpSum(s2);
    int w = threadIdx.x >> 5, l = threadIdx.x & 31;
    if (l == 0) { sh[0][w] = s; sh[1][w] = s2; }
    __syncthreads();
    if (w == 0) {
        float a = (l < 8) ? sh[0][l] : 0.f;
        float c = (l < 8) ? sh[1][l] : 0.f;
        a = warpSum(a); c = warpSum(c);
        if (l == 0) { sh[0][0] = a; sh[1][0] = c; }
    }
    __syncthreads();
    float mu  = sh[0][0] * (1.f / DIMD);
    float var = sh[1][0] * (1.f / DIMD) - mu * mu;
    float rs  = rsqrtf(var + 1e-6f);
    __half* orow = out + (size_t)row * DIMD;
#pragma unroll
    for (int j = 0; j < 4; j++) {
        int c = threadIdx.x + 256 * j;
        orow[c] = __float2half((v[j] - mu) * rs * g[c] + b[c]);
    }
}

// ------- q: l2norm + a = SCALE*dot(qn, wg) fused (one warp per row) -------
__global__ void rownorm_adot_kernel(__half* __restrict__ q,
                                    const float* __restrict__ wg,
                                    float* __restrict__ a) {
    int row  = blockIdx.x * 8 + (threadIdx.x >> 5);
    int lane = threadIdx.x & 31;
    float4* r = (float4*)(q + (size_t)row * ADIMD);
    float4 v = r[lane];
    __half2* h2 = (__half2*)&v;
    float s = 0.f;
    float2 f[4];
#pragma unroll
    for (int i = 0; i < 4; i++) {
        f[i] = __half22float2(h2[i]);
        s += f[i].x * f[i].x + f[i].y * f[i].y;
    }
    s = warpSum(s);
    float inv = 1.0f / fmaxf(sqrtf(s), 1e-12f);
    const float4* w4 = (const float4*)wg;
    float4 w0 = w4[lane * 2], w1 = w4[lane * 2 + 1];
    float d = 0.f;
#pragma unroll
    for (int i = 0; i < 4; i++) {
        f[i].x *= inv; f[i].y *= inv;
        h2[i] = __floats2half2_rn(f[i].x, f[i].y);
    }
    d = f[0].x * w0.x + f[0].y * w0.y + f[1].x * w0.z + f[1].y * w0.w
      + f[2].x * w1.x + f[2].y * w1.y + f[3].x * w1.z + f[3].y * w1.w;
    d = warpSum(d);
    r[lane] = v;
    if (lane == 0) a[row] = d * SCALE_A;
}

// ---------------- plain row l2norm for k ----------------------------------
__global__ void rownorm_kernel(__half* __restrict__ q) {
    int row  = blockIdx.x * 8 + (threadIdx.x >> 5);
    int lane = threadIdx.x & 31;
    float4* r = (float4*)(q + (size_t)row * ADIMD);
    float4 v = r[lane];
    __half2* h2 = (__half2*)&v;
    float s = 0.f;
    float2 f[4];
#pragma unroll
    for (int i = 0; i < 4; i++) {
        f[i] = __half22float2(h2[i]);
        s += f[i].x * f[i].x + f[i].y * f[i].y;
    }
    s = warpSum(s);
    float inv = 1.0f / fmaxf(sqrtf(s), 1e-12f);
#pragma unroll
    for (int i = 0; i < 4; i++)
        h2[i] = __floats2half2_rn(f[i].x * inv, f[i].y * inv);
    r[lane] = v;
}

__global__ void anorm_kernel(const float* __restrict__ a, float* __restrict__ rn) {
    int b = blockIdx.x;
    float s = 0.f;
    for (int n = threadIdx.x; n < NTOK; n += 256) {
        float v = a[b * NTOK + n];
        s += v * v;
    }
    __shared__ float sh[8];
    s = warpSum(s);
    int w = threadIdx.x >> 5, l = threadIdx.x & 31;
    if (l == 0) sh[w] = s;
    __syncthreads();
    if (w == 0) {
        float v = (l < 8) ? sh[l] : 0.f;
        v = warpSum(v);
        if (l == 0) rn[b] = 1.0f / fmaxf(sqrtf(v), 1e-12f);
    }
}

__global__ void gsum1_kernel(const __half* __restrict__ q,
                             const float* __restrict__ a,
                             float* __restrict__ Gp) {
    int b  = blockIdx.x >> 5;
    int ch = blockIdx.x & 31;
    int c  = threadIdx.x;
    const __half* qb = q + ((size_t)b * NTOK + (size_t)ch * 128) * ADIMD;
    const float* ab = a + b * NTOK + ch * 128;
    float s = 0.f;
#pragma unroll 4
    for (int n = 0; n < 128; n++)
        s += ab[n] * __half2float(qb[(size_t)n * ADIMD + c]);
    Gp[(size_t)blockIdx.x * ADIMD + c] = s;
}

__global__ void gsum2_kernel(const float* __restrict__ Gp,
                             const float* __restrict__ rn,
                             float* __restrict__ G) {
    int b = blockIdx.x;
    int c = threadIdx.x;
    float s = 0.f;
#pragma unroll
    for (int ch = 0; ch < 32; ch++)
        s += Gp[((size_t)b * 32 + ch) * ADIMD + c];
    G[b * ADIMD + c] = s * rn[b];
}

__global__ void kscale_kernel(__half* __restrict__ k, const float* __restrict__ G) {
    int idx = blockIdx.x * 1024 + threadIdx.x;      // over half2 pairs
    int e = idx * 2;
    int b = e >> 20;
    int c = e & 255;
    __half2* kp = (__half2*)k + idx;
    float2 f = __half22float2(*kp);
    *kp = __floats2half2_rn(f.x * G[b * ADIMD + c], f.y * G[b * ADIMD + c + 1]);
}

// ---------------- host orchestration --------------------------------------
extern "C" void kernel_launch(void* const* d_in, const int* in_sizes, int n_in,
                              void* d_out, int out_size) {
    const float* x_in  = (const float*)d_in[0];
    const float* ln1_g = (const float*)d_in[1];
    const float* ln1_b = (const float*)d_in[2];
    const float* Wq    = (const float*)d_in[3];
    const float* bq    = (const float*)d_in[4];
    const float* Wk    = (const float*)d_in[5];
    const float* bk    = (const float*)d_in[6];
    const float* w_g   = (const float*)d_in[7];
    const float* Wp    = (const float*)d_in[8];
    const float* bp    = (const float*)d_in[9];
    const float* Wf    = (const float*)d_in[10];
    const float* bf    = (const float*)d_in[11];
    const float* ln2_g = (const float*)d_in[12];
    const float* ln2_b = (const float*)d_in[13];
    const float* W1    = (const float*)d_in[14];
    const float* b1    = (const float*)d_in[15];
    const float* W2    = (const float*)d_in[16];
    const float* b2    = (const float*)d_in[17];

    float* x = (float*)d_out;

    void* p;
    cudaGetSymbolAddress(&p, g_h);   __half* h   = (__half*)p;
    cudaGetSymbolAddress(&p, g_q);   __half* q   = (__half*)p;
    cudaGetSymbolAddress(&p, g_k);   __half* k   = (__half*)p;
    cudaGetSymbolAddress(&p, g_att); __half* att = (__half*)p;
    cudaGetSymbolAddress(&p, g_hid); __half* hid = (__half*)p;
    cudaGetSymbolAddress(&p, g_a);   float* a    = (float*)p;
    cudaGetSymbolAddress(&p, g_rn);  float* rn   = (float*)p;
    cudaGetSymbolAddress(&p, g_G);   float* G    = (float*)p;
    cudaGetSymbolAddress(&p, g_Gp);  float* Gp   = (float*)p;
    cudaGetSymbolAddress(&p, g_Wqt); __half* Wqt = (__half*)p;
    cudaGetSymbolAddress(&p, g_Wkt); __half* Wkt = (__half*)p;
    cudaGetSymbolAddress(&p, g_Wpt); __half* Wpt = (__half*)p;
    cudaGetSymbolAddress(&p, g_Wft); __half* Wft = (__half*)p;
    cudaGetSymbolAddress(&p, g_W1t); __half* W1t = (__half*)p;
    cudaGetSymbolAddress(&p, g_W2t); __half* W2t = (__half*)p;

    cudaFuncSetAttribute(hgemm<0>, cudaFuncAttributeMaxDynamicSharedMemorySize, SMEM_HGEMM);
    cudaFuncSetAttribute(hgemm<1>, cudaFuncAttributeMaxDynamicSharedMemorySize, SMEM_HGEMM);
    cudaFuncSetAttribute(hgemm<2>, cudaFuncAttributeMaxDynamicSharedMemorySize, SMEM_HGEMM);
    cudaFuncSetAttribute(hgemm<3>, cudaFuncAttributeMaxDynamicSharedMemorySize, SMEM_HGEMM);

    cudaMemcpyAsync(x, x_in, sizeof(float) * (size_t)MROWS * DIMD,
                    cudaMemcpyDeviceToDevice);

    dim3 tb(32, 8);
    for (int i = 0; i < DEPTH; i++) {
        transpose_half<<<dim3(ADIMD/32, DIMD/32), tb>>>(Wq + (size_t)i*DIMD*ADIMD, Wqt + (size_t)i*ADIMD*DIMD, DIMD, ADIMD);
        transpose_half<<<dim3(ADIMD/32, DIMD/32), tb>>>(Wk + (size_t)i*DIMD*ADIMD, Wkt + (size_t)i*ADIMD*DIMD, DIMD, ADIMD);
        transpose_half<<<dim3(ADIMD/32, ADIMD/32), tb>>>(Wp + (size_t)i*ADIMD*ADIMD, Wpt + (size_t)i*ADIMD*ADIMD, ADIMD, ADIMD);
        transpose_half<<<dim3(DIMD/32, ADIMD/32), tb>>>(Wf + (size_t)i*ADIMD*DIMD, Wft + (size_t)i*DIMD*ADIMD, ADIMD, DIMD);
        transpose_half<<<dim3(HIDD/32, DIMD/32), tb>>>(W1 + (size_t)i*DIMD*HIDD, W1t + (size_t)i*HIDD*DIMD, DIMD, HIDD);
        transpose_half<<<dim3(DIMD/32, HIDD/32), tb>>>(W2 + (size_t)i*HIDD*DIMD, W2t + (size_t)i*DIMD*HIDD, HIDD, DIMD);
    }

    const dim3 gQK (ADIMD / 256, MROWS / 128);   // (1, 128)
    const dim3 gDIM(DIMD  / 256, MROWS / 128);   // (4, 128)
    const dim3 gHID(HIDD  / 256, MROWS / 128);   // (16, 128)

    for (int i = 0; i < DEPTH; i++) {
        const __half* Wqt_i = Wqt + (size_t)i * ADIMD * DIMD;
        const __half* Wkt_i = Wkt + (size_t)i * ADIMD * DIMD;
        const __half* Wpt_i = Wpt + (size_t)i * ADIMD * ADIMD;
        const __half* Wft_i = Wft + (size_t)i * DIMD * ADIMD;
        const __half* W1t_i = W1t + (size_t)i * HIDD * DIMD;
        const __half* W2t_i = W2t + (size_t)i * DIMD * HIDD;

        ln_kernel<<<MROWS, 256>>>(x, ln1_g + i * DIMD, ln1_b + i * DIMD, h);
        hgemm<0><<<gQK, 256, SMEM_HGEMM>>>(ADIMD, DIMD, h, Wqt_i, bq + i * ADIMD, nullptr, q);
        hgemm<0><<<gQK, 256, SMEM_HGEMM>>>(ADIMD, DIMD, h, Wkt_i, bk + i * ADIMD, nullptr, k);
        rownorm_adot_kernel<<<MROWS / 8, 256>>>(q, w_g + i * ADIMD, a);
        rownorm_kernel<<<MROWS / 8, 256>>>(k);
        anorm_kernel<<<NB, 256>>>(a, rn);
        gsum1_kernel<<<NB * 32, ADIMD>>>(q, a, Gp);
        gsum2_kernel<<<NB, ADIMD>>>(Gp, rn, G);
        kscale_kernel<<<(MROWS * ADIMD / 2) / 1024, 1024>>>(k, G);
        hgemm<3><<<gQK, 256, SMEM_HGEMM>>>(ADIMD, ADIMD, k, Wpt_i, bp + i * ADIMD, q, att);
        hgemm<1><<<gDIM, 256, SMEM_HGEMM>>>(DIMD, ADIMD, att, Wft_i, bf + i * DIMD, nullptr, x);
        ln_kernel<<<MROWS, 256>>>(x, ln2_g + i * DIMD, ln2_b + i * DIMD, h);
        hgemm<2><<<gHID, 256, SMEM_HGEMM>>>(HIDD, DIMD, h, W1t_i, b1 + i * HIDD, nullptr, hid);
        hgemm<1><<<gDIM, 256, SMEM_HGEMM>>>(DIMD, HIDD, hid, W2t_i, b2 + i * DIMD, nullptr, x);
    }
}

// round 8
// speedup vs baseline: 1.2730x; 1.2730x over previous
#include <cuda_runtime.h>
#include <cuda_fp16.h>
#include <math.h>
#include <stdint.h>

#define DIMD  1024
#define ADIMD 256
#define HIDD  4096
#define NTOK  4096
#define NB    4
#define MROWS (NB * NTOK)        // 16384
#define DEPTH 4
#define SCALE_A 0.25f

// ---------------- scratch (device globals) ----------------
__device__ __half g_h  [(size_t)MROWS * DIMD];
__device__ __half g_q  [(size_t)MROWS * ADIMD];
__device__ __half g_k  [(size_t)MROWS * ADIMD];
__device__ __half g_att[(size_t)MROWS * ADIMD];
__device__ __half g_hid[(size_t)MROWS * HIDD];
__device__ float  g_a  [MROWS];
__device__ float  g_rn [NB];
__device__ float  g_G  [NB * ADIMD];
__device__ float  g_Gp [NB * 32 * ADIMD];
__device__ __half g_Wqt[(size_t)DEPTH * ADIMD * DIMD];
__device__ __half g_Wkt[(size_t)DEPTH * ADIMD * DIMD];
__device__ __half g_Wpt[(size_t)DEPTH * ADIMD * ADIMD];
__device__ __half g_Wft[(size_t)DEPTH * DIMD * ADIMD];
__device__ __half g_W1t[(size_t)DEPTH * HIDD * DIMD];
__device__ __half g_W2t[(size_t)DEPTH * DIMD * HIDD];

// ---------------- helpers ----------------
__device__ __forceinline__ float warpSum(float v) {
#pragma unroll
    for (int o = 16; o > 0; o >>= 1) v += __shfl_xor_sync(0xFFFFFFFFu, v, o);
    return v;
}
__device__ __forceinline__ uint32_t smem_u32(const void* p) {
    uint32_t a;
    asm("{ .reg .u64 t; cvta.to.shared.u64 t, %1; cvt.u32.u64 %0, t; }" : "=r"(a) : "l"(p));
    return a;
}
__device__ __forceinline__ void cp_async16(uint32_t saddr, const void* g) {
    asm volatile("cp.async.cg.shared.global [%0], [%1], 16;" :: "r"(saddr), "l"(g));
}
__device__ __forceinline__ void cp_commit() { asm volatile("cp.async.commit_group;"); }
template <int N> __device__ __forceinline__ void cp_wait() {
    asm volatile("cp.async.wait_group %0;" :: "n"(N));
}
__device__ __forceinline__ void ldsm4(uint32_t& r0, uint32_t& r1, uint32_t& r2, uint32_t& r3,
                                      uint32_t addr) {
    asm volatile("ldmatrix.sync.aligned.m8n8.x4.shared.b16 {%0,%1,%2,%3}, [%4];"
                 : "=r"(r0), "=r"(r1), "=r"(r2), "=r"(r3) : "r"(addr));
}
__device__ __forceinline__ void mma_f16(float& c0, float& c1, float& c2, float& c3,
                                        uint32_t a0, uint32_t a1, uint32_t a2, uint32_t a3,
                                        uint32_t b0, uint32_t b1) {
    asm volatile(
        "mma.sync.aligned.m16n8k16.row.col.f32.f16.f16.f32 "
        "{%0,%1,%2,%3}, {%4,%5,%6,%7}, {%8,%9}, {%0,%1,%2,%3};"
        : "+f"(c0), "+f"(c1), "+f"(c2), "+f"(c3)
        : "r"(a0), "r"(a1), "r"(a2), "r"(a3), "r"(b0), "r"(b1));
}

// ======= fp16 pipelined GEMM: CTA 128x128x32, warps 2x4 of 64x32, 4 stages =
#define A_BYTES     10240                 // 128 rows x 40 halfs (80B)
#define STAGE_BYTES 20480                 // A + B
#define NSTAGE      4
#define SMEM_HGEMM  (NSTAGE * STAGE_BYTES)  // 81920

// EPI: 0 = half(AB+bias) | 1 = Cf32 += AB+bias | 2 = half(gelu(AB+bias))
//      3 = half(AB+bias+D)
template <int EPI>
__global__ __launch_bounds__(256, 2)
void hgemm(int N, int K,
           const __half* __restrict__ A,     // [M][K]
           const __half* __restrict__ Bt,    // [N][K]
           const float* __restrict__ bias,   // [N]
           const __half* __restrict__ Dadd,  // [M][N] (EPI 3)
           void* __restrict__ Cv) {
    extern __shared__ char smraw[];
    const uint32_t sbase = smem_u32(smraw);

    const int bx = blockIdx.x, by = blockIdx.y;
    const int tid = threadIdx.x;
    const int lane = tid & 31;
    const int warp = tid >> 5;
    const int warpM = warp & 1;         // 2 warps over M (64 rows)
    const int warpN = warp >> 1;        // 4 warps over N (32 cols)
    const int tg  = lane & 3;

    const __half* Ab = A  + (size_t)by * 128 * K;
    const __half* Bb = Bt + (size_t)bx * 128 * K;

    const uint32_t a_lane = (uint32_t)((warpM * 64 + (lane & 15)) * 80 + (lane >> 4) * 16);
    const uint32_t b_lane = (uint32_t)(A_BYTES +
        (warpN * 32 + (lane & 7) + 8 * (lane >> 4)) * 80 + ((lane >> 3) & 1) * 16);

    float acc[4][4][4];
#pragma unroll
    for (int mi = 0; mi < 4; mi++)
#pragma unroll
        for (int ni = 0; ni < 4; ni++)
#pragma unroll
            for (int r = 0; r < 4; r++) acc[mi][ni][r] = 0.f;

    const int T = K / 32;

#define LOAD_TILE(t_, s_) do {                                                \
        uint32_t _sa = sbase + (s_) * STAGE_BYTES;                            \
        uint32_t _sb = _sa + A_BYTES;                                         \
        const __half* _ga = Ab + (size_t)(t_) * 32;                          \
        const __half* _gb = Bb + (size_t)(t_) * 32;                          \
        _Pragma("unroll")                                                     \
        for (int _i = 0; _i < 2; _i++) {                                      \
            int _id = tid + _i * 256;                                         \
            int _r = _id >> 2, _c = _id & 3;                                  \
            cp_async16(_sa + _r * 80 + _c * 16, _ga + (size_t)_r * K + _c * 8); \
            cp_async16(_sb + _r * 80 + _c * 16, _gb + (size_t)_r * K + _c * 8); \
        }                                                                     \
        cp_commit();                                                          \
    } while (0)

    // prologue: 3 tiles in flight
    LOAD_TILE(0, 0);
    if (T > 1) LOAD_TILE(1, 1); else cp_commit();
    if (T > 2) LOAD_TILE(2, 2); else cp_commit();

    for (int t = 0; t < T; t++) {
        cp_wait<2>();                 // tile t resident
        __syncthreads();              // also orders last reads of slot (t+3)%4
        if (t + 3 < T) LOAD_TILE(t + 3, (t + 3) % NSTAGE);
        else cp_commit();

        const uint32_t st = sbase + (t % NSTAGE) * STAGE_BYTES;
        const uint32_t a0addr = st + a_lane;
        const uint32_t b0addr = st + b_lane;
#pragma unroll
        for (int ks = 0; ks < 2; ks++) {
            uint32_t af[4][4], bfr[4][2];
#pragma unroll
            for (int mi = 0; mi < 4; mi++)
                ldsm4(af[mi][0], af[mi][1], af[mi][2], af[mi][3],
                      a0addr + mi * 1280 + ks * 32);
#pragma unroll
            for (int p = 0; p < 2; p++)
                ldsm4(bfr[2 * p][0], bfr[2 * p][1], bfr[2 * p + 1][0], bfr[2 * p + 1][1],
                      b0addr + p * 1280 + ks * 32);
#pragma unroll
            for (int mi = 0; mi < 4; mi++)
#pragma unroll
                for (int ni = 0; ni < 4; ni++)
                    mma_f16(acc[mi][ni][0], acc[mi][ni][1],
                            acc[mi][ni][2], acc[mi][ni][3],
                            af[mi][0], af[mi][1], af[mi][2], af[mi][3],
                            bfr[ni][0], bfr[ni][1]);
        }
    }

    // epilogue
    const int grp8 = lane >> 2;
#pragma unroll
    for (int mi = 0; mi < 4; mi++) {
#pragma unroll
        for (int ni = 0; ni < 4; ni++) {
            int col = bx * 128 + warpN * 32 + ni * 8 + 2 * tg;
            int row0 = by * 128 + warpM * 64 + mi * 16 + grp8;
            float bv0 = bias[col], bv1 = bias[col + 1];
#pragma unroll
            for (int hh = 0; hh < 2; hh++) {
                int row = row0 + hh * 8;
                float v0 = acc[mi][ni][hh * 2 + 0] + bv0;
                float v1 = acc[mi][ni][hh * 2 + 1] + bv1;
                if (EPI == 1) {
                    float* Cp = (float*)Cv + (size_t)row * N + col;
                    float2 old = *(const float2*)Cp;
                    *(float2*)Cp = make_float2(v0 + old.x, v1 + old.y);
                } else {
                    __half* Cp = (__half*)Cv + (size_t)row * N + col;
                    if (EPI == 2) {
                        v0 = 0.5f * v0 * (1.0f + erff(v0 * 0.70710678118654752f));
                        v1 = 0.5f * v1 * (1.0f + erff(v1 * 0.70710678118654752f));
                    }
                    if (EPI == 3) {
                        float2 dv = __half22float2(
                            *(const __half2*)(Dadd + (size_t)row * N + col));
                        v0 += dv.x; v1 += dv.y;
                    }
                    *(__half2*)Cp = __floats2half2_rn(v0, v1);
                }
            }
        }
    }
}

// ------- batched weight transpose (z = layer): W[K][N] -> Wt[N][K] fp16 ----
__global__ void transpose_half(const float* __restrict__ W, __half* __restrict__ Wt,
                               int K, int N) {
    __shared__ float t[32][33];
    const size_t lofW = (size_t)blockIdx.z * K * N;
    int n0 = blockIdx.x * 32, k0 = blockIdx.y * 32;
    int tx = threadIdx.x, ty = threadIdx.y;     // 32 x 8
#pragma unroll
    for (int i = 0; i < 4; i++)
        t[ty + 8 * i][tx] = W[lofW + (size_t)(k0 + ty + 8 * i) * N + n0 + tx];
    __syncthreads();
#pragma unroll
    for (int i = 0; i < 4; i++)
        Wt[lofW + (size_t)(n0 + ty + 8 * i) * K + k0 + tx] = __float2half(t[tx][ty + 8 * i]);
}

// ---------------- LayerNorm (fp32 in, fp16 out) ---------------------------
__global__ void ln_kernel(const float* __restrict__ x,
                          const float* __restrict__ g,
                          const float* __restrict__ b,
                          __half* __restrict__ out) {
    int row = blockIdx.x;
    const float* xr = x + (size_t)row * DIMD;
    float v[4];
    float s = 0.f, s2 = 0.f;
#pragma unroll
    for (int j = 0; j < 4; j++) {
        v[j] = xr[threadIdx.x + 256 * j];
        s += v[j]; s2 += v[j] * v[j];
    }
    __shared__ float sh[2][8];
    s = warpSum(s); s2 = warpSum(s2);
    int w = threadIdx.x >> 5, l = threadIdx.x & 31;
    if (l == 0) { sh[0][w] = s; sh[1][w] = s2; }
    __syncthreads();
    if (w == 0) {
        float a = (l < 8) ? sh[0][l] : 0.f;
        float c = (l < 8) ? sh[1][l] : 0.f;
        a = warpSum(a); c = warpSum(c);
        if (l == 0) { sh[0][0] = a; sh[1][0] = c; }
    }
    __syncthreads();
    float mu  = sh[0][0] * (1.f / DIMD);
    float var = sh[1][0] * (1.f / DIMD) - mu * mu;
    float rs  = rsqrtf(var + 1e-6f);
    __half* orow = out + (size_t)row * DIMD;
#pragma unroll
    for (int j = 0; j < 4; j++) {
        int c = threadIdx.x + 256 * j;
        orow[c] = __float2half((v[j] - mu) * rs * g[c] + b[c]);
    }
}

// ------- q: l2norm + a = SCALE*dot(qn, wg) fused (one warp per row) -------
__global__ void rownorm_adot_kernel(__half* __restrict__ q,
                                    const float* __restrict__ wg,
                                    float* __restrict__ a) {
    int row  = blockIdx.x * 8 + (threadIdx.x >> 5);
    int lane = threadIdx.x & 31;
    float4* r = (float4*)(q + (size_t)row * ADIMD);
    float4 v = r[lane];
    __half2* h2 = (__half2*)&v;
    float s = 0.f;
    float2 f[4];
#pragma unroll
    for (int i = 0; i < 4; i++) {
        f[i] = __half22float2(h2[i]);
        s += f[i].x * f[i].x + f[i].y * f[i].y;
    }
    s = warpSum(s);
    float inv = 1.0f / fmaxf(sqrtf(s), 1e-12f);
    const float4* w4 = (const float4*)wg;
    float4 w0 = w4[lane * 2], w1 = w4[lane * 2 + 1];
    float d = 0.f;
#pragma unroll
    for (int i = 0; i < 4; i++) {
        f[i].x *= inv; f[i].y *= inv;
        h2[i] = __floats2half2_rn(f[i].x, f[i].y);
    }
    d = f[0].x * w0.x + f[0].y * w0.y + f[1].x * w0.z + f[1].y * w0.w
      + f[2].x * w1.x + f[2].y * w1.y + f[3].x * w1.z + f[3].y * w1.w;
    d = warpSum(d);
    r[lane] = v;
    if (lane == 0) a[row] = d * SCALE_A;
}

// ---------------- plain row l2norm for k ----------------------------------
__global__ void rownorm_kernel(__half* __restrict__ q) {
    int row  = blockIdx.x * 8 + (threadIdx.x >> 5);
    int lane = threadIdx.x & 31;
    float4* r = (float4*)(q + (size_t)row * ADIMD);
    float4 v = r[lane];
    __half2* h2 = (__half2*)&v;
    float s = 0.f;
    float2 f[4];
#pragma unroll
    for (int i = 0; i < 4; i++) {
        f[i] = __half22float2(h2[i]);
        s += f[i].x * f[i].x + f[i].y * f[i].y;
    }
    s = warpSum(s);
    float inv = 1.0f / fmaxf(sqrtf(s), 1e-12f);
#pragma unroll
    for (int i = 0; i < 4; i++)
        h2[i] = __floats2half2_rn(f[i].x * inv, f[i].y * inv);
    r[lane] = v;
}

__global__ void anorm_kernel(const float* __restrict__ a, float* __restrict__ rn) {
    int b = blockIdx.x;
    float s = 0.f;
    for (int n = threadIdx.x; n < NTOK; n += 256) {
        float v = a[b * NTOK + n];
        s += v * v;
    }
    __shared__ float sh[8];
    s = warpSum(s);
    int w = threadIdx.x >> 5, l = threadIdx.x & 31;
    if (l == 0) sh[w] = s;
    __syncthreads();
    if (w == 0) {
        float v = (l < 8) ? sh[l] : 0.f;
        v = warpSum(v);
        if (l == 0) rn[b] = 1.0f / fmaxf(sqrtf(v), 1e-12f);
    }
}

__global__ void gsum1_kernel(const __half* __restrict__ q,
                             const float* __restrict__ a,
                             float* __restrict__ Gp) {
    int b  = blockIdx.x >> 5;
    int ch = blockIdx.x & 31;
    int c  = threadIdx.x;
    const __half* qb = q + ((size_t)b * NTOK + (size_t)ch * 128) * ADIMD;
    const float* ab = a + b * NTOK + ch * 128;
    float s = 0.f;
#pragma unroll 4
    for (int n = 0; n < 128; n++)
        s += ab[n] * __half2float(qb[(size_t)n * ADIMD + c]);
    Gp[(size_t)blockIdx.x * ADIMD + c] = s;
}

__global__ void gsum2_kernel(const float* __restrict__ Gp,
                             const float* __restrict__ rn,
                             float* __restrict__ G) {
    int b = blockIdx.x;
    int c = threadIdx.x;
    float s = 0.f;
#pragma unroll
    for (int ch = 0; ch < 32; ch++)
        s += Gp[((size_t)b * 32 + ch) * ADIMD + c];
    G[b * ADIMD + c] = s * rn[b];
}

__global__ void kscale_kernel(__half* __restrict__ k, const float* __restrict__ G) {
    int idx = blockIdx.x * 1024 + threadIdx.x;      // over half2 pairs
    int e = idx * 2;
    int b = e >> 20;
    int c = e & 255;
    __half2* kp = (__half2*)k + idx;
    float2 f = __half22float2(*kp);
    *kp = __floats2half2_rn(f.x * G[b * ADIMD + c], f.y * G[b * ADIMD + c + 1]);
}

// ---------------- host orchestration --------------------------------------
extern "C" void kernel_launch(void* const* d_in, const int* in_sizes, int n_in,
                              void* d_out, int out_size) {
    const float* x_in  = (const float*)d_in[0];
    const float* ln1_g = (const float*)d_in[1];
    const float* ln1_b = (const float*)d_in[2];
    const float* Wq    = (const float*)d_in[3];
    const float* bq    = (const float*)d_in[4];
    const float* Wk    = (const float*)d_in[5];
    const float* bk    = (const float*)d_in[6];
    const float* w_g   = (const float*)d_in[7];
    const float* Wp    = (const float*)d_in[8];
    const float* bp    = (const float*)d_in[9];
    const float* Wf    = (const float*)d_in[10];
    const float* bf    = (const float*)d_in[11];
    const float* ln2_g = (const float*)d_in[12];
    const float* ln2_b = (const float*)d_in[13];
    const float* W1    = (const float*)d_in[14];
    const float* b1    = (const float*)d_in[15];
    const float* W2    = (const float*)d_in[16];
    const float* b2    = (const float*)d_in[17];

    float* x = (float*)d_out;

    void* p;
    cudaGetSymbolAddress(&p, g_h);   __half* h   = (__half*)p;
    cudaGetSymbolAddress(&p, g_q);   __half* q   = (__half*)p;
    cudaGetSymbolAddress(&p, g_k);   __half* k   = (__half*)p;
    cudaGetSymbolAddress(&p, g_att); __half* att = (__half*)p;
    cudaGetSymbolAddress(&p, g_hid); __half* hid = (__half*)p;
    cudaGetSymbolAddress(&p, g_a);   float* a    = (float*)p;
    cudaGetSymbolAddress(&p, g_rn);  float* rn   = (float*)p;
    cudaGetSymbolAddress(&p, g_G);   float* G    = (float*)p;
    cudaGetSymbolAddress(&p, g_Gp);  float* Gp   = (float*)p;
    cudaGetSymbolAddress(&p, g_Wqt); __half* Wqt = (__half*)p;
    cudaGetSymbolAddress(&p, g_Wkt); __half* Wkt = (__half*)p;
    cudaGetSymbolAddress(&p, g_Wpt); __half* Wpt = (__half*)p;
    cudaGetSymbolAddress(&p, g_Wft); __half* Wft = (__half*)p;
    cudaGetSymbolAddress(&p, g_W1t); __half* W1t = (__half*)p;
    cudaGetSymbolAddress(&p, g_W2t); __half* W2t = (__half*)p;

    cudaFuncSetAttribute(hgemm<0>, cudaFuncAttributeMaxDynamicSharedMemorySize, SMEM_HGEMM);
    cudaFuncSetAttribute(hgemm<1>, cudaFuncAttributeMaxDynamicSharedMemorySize, SMEM_HGEMM);
    cudaFuncSetAttribute(hgemm<2>, cudaFuncAttributeMaxDynamicSharedMemorySize, SMEM_HGEMM);
    cudaFuncSetAttribute(hgemm<3>, cudaFuncAttributeMaxDynamicSharedMemorySize, SMEM_HGEMM);

    cudaMemcpyAsync(x, x_in, sizeof(float) * (size_t)MROWS * DIMD,
                    cudaMemcpyDeviceToDevice);

    // batched transposes: one launch per weight type, z = layer
    dim3 tb(32, 8);
    transpose_half<<<dim3(ADIMD/32, DIMD/32, DEPTH), tb>>>(Wq, Wqt, DIMD, ADIMD);
    transpose_half<<<dim3(ADIMD/32, DIMD/32, DEPTH), tb>>>(Wk, Wkt, DIMD, ADIMD);
    transpose_half<<<dim3(ADIMD/32, ADIMD/32, DEPTH), tb>>>(Wp, Wpt, ADIMD, ADIMD);
    transpose_half<<<dim3(DIMD/32, ADIMD/32, DEPTH), tb>>>(Wf, Wft, ADIMD, DIMD);
    transpose_half<<<dim3(HIDD/32, DIMD/32, DEPTH), tb>>>(W1, W1t, DIMD, HIDD);
    transpose_half<<<dim3(DIMD/32, HIDD/32, DEPTH), tb>>>(W2, W2t, HIDD, DIMD);

    const dim3 gQK (ADIMD / 128, MROWS / 128);   // (2, 128)
    const dim3 gDIM(DIMD  / 128, MROWS / 128);   // (8, 128)
    const dim3 gHID(HIDD  / 128, MROWS / 128);   // (32, 128)

    for (int i = 0; i < DEPTH; i++) {
        const __half* Wqt_i = Wqt + (size_t)i * ADIMD * DIMD;
        const __half* Wkt_i = Wkt + (size_t)i * ADIMD * DIMD;
        const __half* Wpt_i = Wpt + (size_t)i * ADIMD * ADIMD;
        const __half* Wft_i = Wft + (size_t)i * DIMD * ADIMD;
        const __half* W1t_i = W1t + (size_t)i * HIDD * DIMD;
        const __half* W2t_i = W2t + (size_t)i * DIMD * HIDD;

        ln_kernel<<<MROWS, 256>>>(x, ln1_g + i * DIMD, ln1_b + i * DIMD, h);
        hgemm<0><<<gQK, 256, SMEM_HGEMM>>>(ADIMD, DIMD, h, Wqt_i, bq + i * ADIMD, nullptr, q);
        hgemm<0><<<gQK, 256, SMEM_HGEMM>>>(ADIMD, DIMD, h, Wkt_i, bk + i * ADIMD, nullptr, k);
        rownorm_adot_kernel<<<MROWS / 8, 256>>>(q, w_g + i * ADIMD, a);
        rownorm_kernel<<<MROWS / 8, 256>>>(k);
        anorm_kernel<<<NB, 256>>>(a, rn);
        gsum1_kernel<<<NB * 32, ADIMD>>>(q, a, Gp);
        gsum2_kernel<<<NB, ADIMD>>>(Gp, rn, G);
        kscale_kernel<<<(MROWS * ADIMD / 2) / 1024, 1024>>>(k, G);
        hgemm<3><<<gQK, 256, SMEM_HGEMM>>>(ADIMD, ADIMD, k, Wpt_i, bp + i * ADIMD, q, att);
        hgemm<1><<<gDIM, 256, SMEM_HGEMM>>>(DIMD, ADIMD, att, Wft_i, bf + i * DIMD, nullptr, x);
        ln_kernel<<<MROWS, 256>>>(x, ln2_g + i * DIMD, ln2_b + i * DIMD, h);
        hgemm<2><<<gHID, 256, SMEM_HGEMM>>>(HIDD, DIMD, h, W1t_i, b1 + i * HIDD, nullptr, hid);
        hgemm<1><<<gDIM, 256, SMEM_HGEMM>>>(DIMD, HIDD, hid, W2t_i, b2 + i * DIMD, nullptr, x);
    }
}

// round 9
// speedup vs baseline: 1.2804x; 1.0058x over previous
#include <cuda_runtime.h>
#include <cuda_fp16.h>
#include <math.h>
#include <stdint.h>

#define DIMD  1024
#define ADIMD 256
#define HIDD  4096
#define NTOK  4096
#define NB    4
#define MROWS (NB * NTOK)        // 16384
#define DEPTH 4
#define SCALE_A 0.25f

// ---------------- scratch (device globals) ----------------
__device__ __half g_h  [(size_t)MROWS * DIMD];
__device__ __half g_q  [(size_t)MROWS * ADIMD];
__device__ __half g_k  [(size_t)MROWS * ADIMD];
__device__ __half g_att[(size_t)MROWS * ADIMD];
__device__ __half g_hid[(size_t)MROWS * HIDD];
__device__ float  g_a  [MROWS];
__device__ float  g_G  [NB * ADIMD];
__device__ float  g_Gp [NB * 32 * ADIMD];
__device__ __half g_Wqt[(size_t)DEPTH * ADIMD * DIMD];
__device__ __half g_Wkt[(size_t)DEPTH * ADIMD * DIMD];
__device__ __half g_Wpt[(size_t)DEPTH * ADIMD * ADIMD];
__device__ __half g_Wft[(size_t)DEPTH * DIMD * ADIMD];
__device__ __half g_W1t[(size_t)DEPTH * HIDD * DIMD];
__device__ __half g_W2t[(size_t)DEPTH * DIMD * HIDD];

// ---------------- helpers ----------------
__device__ __forceinline__ float warpSum(float v) {
#pragma unroll
    for (int o = 16; o > 0; o >>= 1) v += __shfl_xor_sync(0xFFFFFFFFu, v, o);
    return v;
}
__device__ __forceinline__ uint32_t smem_u32(const void* p) {
    uint32_t a;
    asm("{ .reg .u64 t; cvta.to.shared.u64 t, %1; cvt.u32.u64 %0, t; }" : "=r"(a) : "l"(p));
    return a;
}
__device__ __forceinline__ void cp_async16(uint32_t saddr, const void* g) {
    asm volatile("cp.async.cg.shared.global [%0], [%1], 16;" :: "r"(saddr), "l"(g));
}
__device__ __forceinline__ void cp_commit() { asm volatile("cp.async.commit_group;"); }
template <int N> __device__ __forceinline__ void cp_wait() {
    asm volatile("cp.async.wait_group %0;" :: "n"(N));
}
__device__ __forceinline__ void ldsm4(uint32_t& r0, uint32_t& r1, uint32_t& r2, uint32_t& r3,
                                      uint32_t addr) {
    asm volatile("ldmatrix.sync.aligned.m8n8.x4.shared.b16 {%0,%1,%2,%3}, [%4];"
                 : "=r"(r0), "=r"(r1), "=r"(r2), "=r"(r3) : "r"(addr));
}
__device__ __forceinline__ void mma_f16(float& c0, float& c1, float& c2, float& c3,
                                        uint32_t a0, uint32_t a1, uint32_t a2, uint32_t a3,
                                        uint32_t b0, uint32_t b1) {
    asm volatile(
        "mma.sync.aligned.m16n8k16.row.col.f32.f16.f16.f32 "
        "{%0,%1,%2,%3}, {%4,%5,%6,%7}, {%8,%9}, {%0,%1,%2,%3};"
        : "+f"(c0), "+f"(c1), "+f"(c2), "+f"(c3)
        : "r"(a0), "r"(a1), "r"(a2), "r"(a3), "r"(b0), "r"(b1));
}

// ======= fp16 pipelined GEMM: CTA 128x128x32, warps 2x4 of 64x32, 4 stages =
#define A_BYTES     10240
#define STAGE_BYTES 20480
#define NSTAGE      4
#define SMEM_HGEMM  (NSTAGE * STAGE_BYTES)  // 81920

// EPI: 0 = half(AB+bias) | 1 = Cf32 += AB+bias | 2 = half(gelu(AB+bias))
//      3 = half(AB+bias+D)
template <int EPI>
__global__ __launch_bounds__(256, 2)
void hgemm(int N, int K,
           const __half* __restrict__ A,
           const __half* __restrict__ Bt,
           const float* __restrict__ bias,
           const __half* __restrict__ Dadd,
           void* __restrict__ Cv) {
    extern __shared__ char smraw[];
    const uint32_t sbase = smem_u32(smraw);

    const int bx = blockIdx.x, by = blockIdx.y;
    const int tid = threadIdx.x;
    const int lane = tid & 31;
    const int warp = tid >> 5;
    const int warpM = warp & 1;
    const int warpN = warp >> 1;
    const int tg  = lane & 3;

    const __half* Ab = A  + (size_t)by * 128 * K;
    const __half* Bb = Bt + (size_t)bx * 128 * K;

    const uint32_t a_lane = (uint32_t)((warpM * 64 + (lane & 15)) * 80 + (lane >> 4) * 16);
    const uint32_t b_lane = (uint32_t)(A_BYTES +
        (warpN * 32 + (lane & 7) + 8 * (lane >> 4)) * 80 + ((lane >> 3) & 1) * 16);

    float acc[4][4][4];
#pragma unroll
    for (int mi = 0; mi < 4; mi++)
#pragma unroll
        for (int ni = 0; ni < 4; ni++)
#pragma unroll
            for (int r = 0; r < 4; r++) acc[mi][ni][r] = 0.f;

    const int T = K / 32;

#define LOAD_TILE(t_, s_) do {                                                \
        uint32_t _sa = sbase + (s_) * STAGE_BYTES;                            \
        uint32_t _sb = _sa + A_BYTES;                                         \
        const __half* _ga = Ab + (size_t)(t_) * 32;                          \
        const __half* _gb = Bb + (size_t)(t_) * 32;                          \
        _Pragma("unroll")                                                     \
        for (int _i = 0; _i < 2; _i++) {                                      \
            int _id = tid + _i * 256;                                         \
            int _r = _id >> 2, _c = _id & 3;                                  \
            cp_async16(_sa + _r * 80 + _c * 16, _ga + (size_t)_r * K + _c * 8); \
            cp_async16(_sb + _r * 80 + _c * 16, _gb + (size_t)_r * K + _c * 8); \
        }                                                                     \
        cp_commit();                                                          \
    } while (0)

    LOAD_TILE(0, 0);
    if (T > 1) LOAD_TILE(1, 1); else cp_commit();
    if (T > 2) LOAD_TILE(2, 2); else cp_commit();

    for (int t = 0; t < T; t++) {
        cp_wait<2>();
        __syncthreads();
        if (t + 3 < T) LOAD_TILE(t + 3, (t + 3) % NSTAGE);
        else cp_commit();

        const uint32_t st = sbase + (t % NSTAGE) * STAGE_BYTES;
        const uint32_t a0addr = st + a_lane;
        const uint32_t b0addr = st + b_lane;
#pragma unroll
        for (int ks = 0; ks < 2; ks++) {
            uint32_t af[4][4], bfr[4][2];
#pragma unroll
            for (int mi = 0; mi < 4; mi++)
                ldsm4(af[mi][0], af[mi][1], af[mi][2], af[mi][3],
                      a0addr + mi * 1280 + ks * 32);
#pragma unroll
            for (int p = 0; p < 2; p++)
                ldsm4(bfr[2 * p][0], bfr[2 * p][1], bfr[2 * p + 1][0], bfr[2 * p + 1][1],
                      b0addr + p * 1280 + ks * 32);
#pragma unroll
            for (int mi = 0; mi < 4; mi++)
#pragma unroll
                for (int ni = 0; ni < 4; ni++)
                    mma_f16(acc[mi][ni][0], acc[mi][ni][1],
                            acc[mi][ni][2], acc[mi][ni][3],
                            af[mi][0], af[mi][1], af[mi][2], af[mi][3],
                            bfr[ni][0], bfr[ni][1]);
        }
    }

    const int grp8 = lane >> 2;
#pragma unroll
    for (int mi = 0; mi < 4; mi++) {
#pragma unroll
        for (int ni = 0; ni < 4; ni++) {
            int col = bx * 128 + warpN * 32 + ni * 8 + 2 * tg;
            int row0 = by * 128 + warpM * 64 + mi * 16 + grp8;
            float bv0 = bias[col], bv1 = bias[col + 1];
#pragma unroll
            for (int hh = 0; hh < 2; hh++) {
                int row = row0 + hh * 8;
                float v0 = acc[mi][ni][hh * 2 + 0] + bv0;
                float v1 = acc[mi][ni][hh * 2 + 1] + bv1;
                if (EPI == 1) {
                    float* Cp = (float*)Cv + (size_t)row * N + col;
                    float2 old = *(const float2*)Cp;
                    *(float2*)Cp = make_float2(v0 + old.x, v1 + old.y);
                } else {
                    __half* Cp = (__half*)Cv + (size_t)row * N + col;
                    if (EPI == 2) {
                        v0 = 0.5f * v0 * (1.0f + erff(v0 * 0.70710678118654752f));
                        v1 = 0.5f * v1 * (1.0f + erff(v1 * 0.70710678118654752f));
                    }
                    if (EPI == 3) {
                        float2 dv = __half22float2(
                            *(const __half2*)(Dadd + (size_t)row * N + col));
                        v0 += dv.x; v1 += dv.y;
                    }
                    *(__half2*)Cp = __floats2half2_rn(v0, v1);
                }
            }
        }
    }
}

// -------- single-launch transpose of ALL weights: W[K][N] -> Wt[N][K] ------
// flat tile ranges: Wq[0,1024) Wk[1024,2048) Wp[2048,2304) Wf[2304,3328)
//                   W1[3328,19712) W2[19712,36096)
#define TRANS_BLOCKS 36096
__global__ void transpose_all(const float* __restrict__ Wq, const float* __restrict__ Wk,
                              const float* __restrict__ Wp, const float* __restrict__ Wf,
                              const float* __restrict__ W1, const float* __restrict__ W2,
                              __half* __restrict__ Wqt, __half* __restrict__ Wkt,
                              __half* __restrict__ Wpt, __half* __restrict__ Wft,
                              __half* __restrict__ W1t, __half* __restrict__ W2t) {
    int id = blockIdx.x;
    const float* W; __half* Wt; int K, N, base;
    if      (id < 1024)  { W = Wq; Wt = Wqt; K = DIMD;  N = ADIMD; base = 0; }
    else if (id < 2048)  { W = Wk; Wt = Wkt; K = DIMD;  N = ADIMD; base = 1024; }
    else if (id < 2304)  { W = Wp; Wt = Wpt; K = ADIMD; N = ADIMD; base = 2048; }
    else if (id < 3328)  { W = Wf; Wt = Wft; K = ADIMD; N = DIMD;  base = 2304; }
    else if (id < 19712) { W = W1; Wt = W1t; K = DIMD;  N = HIDD;  base = 3328; }
    else                 { W = W2; Wt = W2t; K = HIDD;  N = DIMD;  base = 19712; }
    int lid = id - base;
    int ntN = N >> 5;
    int tpl = (K >> 5) * ntN;
    int layer = lid / tpl;
    int rem   = lid % tpl;
    int n0 = (rem % ntN) * 32, k0 = (rem / ntN) * 32;
    size_t off = (size_t)layer * K * N;

    __shared__ float t[32][33];
    int tx = threadIdx.x, ty = threadIdx.y;   // 32 x 8
#pragma unroll
    for (int i = 0; i < 4; i++)
        t[ty + 8 * i][tx] = W[off + (size_t)(k0 + ty + 8 * i) * N + n0 + tx];
    __syncthreads();
#pragma unroll
    for (int i = 0; i < 4; i++)
        Wt[off + (size_t)(n0 + ty + 8 * i) * K + k0 + tx] = __float2half(t[tx][ty + 8 * i]);
}

// ---------------- LayerNorm (fp32 in, fp16 out) ---------------------------
__global__ void ln_kernel(const float* __restrict__ x,
                          const float* __restrict__ g,
                          const float* __restrict__ b,
                          __half* __restrict__ out) {
    int row = blockIdx.x;
    const float* xr = x + (size_t)row * DIMD;
    float v[4];
    float s = 0.f, s2 = 0.f;
#pragma unroll
    for (int j = 0; j < 4; j++) {
        v[j] = xr[threadIdx.x + 256 * j];
        s += v[j]; s2 += v[j] * v[j];
    }
    __shared__ float sh[2][8];
    s = warpSum(s); s2 = warpSum(s2);
    int w = threadIdx.x >> 5, l = threadIdx.x & 31;
    if (l == 0) { sh[0][w] = s; sh[1][w] = s2; }
    __syncthreads();
    if (w == 0) {
        float a = (l < 8) ? sh[0][l] : 0.f;
        float c = (l < 8) ? sh[1][l] : 0.f;
        a = warpSum(a); c = warpSum(c);
        if (l == 0) { sh[0][0] = a; sh[1][0] = c; }
    }
    __syncthreads();
    float mu  = sh[0][0] * (1.f / DIMD);
    float var = sh[1][0] * (1.f / DIMD) - mu * mu;
    float rs  = rsqrtf(var + 1e-6f);
    __half* orow = out + (size_t)row * DIMD;
#pragma unroll
    for (int j = 0; j < 4; j++) {
        int c = threadIdx.x + 256 * j;
        orow[c] = __float2half((v[j] - mu) * rs * g[c] + b[c]);
    }
}

// ---- fused q pipeline: l2norm rows + a=SCALE*dot(qn,wg) + Gp partial -----
// block = 256 threads handles 128 consecutive rows (8 warps x 16 rows)
__global__ void rnq_gsum_kernel(__half* __restrict__ q,
                                const float* __restrict__ wg,
                                float* __restrict__ a_out,
                                float* __restrict__ Gp) {
    __shared__ float a_sh[128];
    const int warp = threadIdx.x >> 5, lane = threadIdx.x & 31;
    const int row0 = blockIdx.x * 128;
    const float4* w4 = (const float4*)wg;
    const float4 w0 = w4[lane * 2], w1 = w4[lane * 2 + 1];

#pragma unroll 4
    for (int i = 0; i < 16; i++) {
        int r = warp * 16 + i;
        int row = row0 + r;
        float4* rp = (float4*)(q + (size_t)row * ADIMD);
        float4 v = rp[lane];
        __half2* h2 = (__half2*)&v;
        float2 f[4];
        float s = 0.f;
#pragma unroll
        for (int j = 0; j < 4; j++) {
            f[j] = __half22float2(h2[j]);
            s += f[j].x * f[j].x + f[j].y * f[j].y;
        }
        s = warpSum(s);
        float inv = 1.0f / fmaxf(sqrtf(s), 1e-12f);
#pragma unroll
        for (int j = 0; j < 4; j++) {
            f[j].x *= inv; f[j].y *= inv;
            h2[j] = __floats2half2_rn(f[j].x, f[j].y);
        }
        float d = f[0].x * w0.x + f[0].y * w0.y + f[1].x * w0.z + f[1].y * w0.w
                + f[2].x * w1.x + f[2].y * w1.y + f[3].x * w1.z + f[3].y * w1.w;
        d = warpSum(d);
        rp[lane] = v;
        if (lane == 0) {
            float av = d * SCALE_A;
            a_sh[r] = av;
            a_out[row] = av;
        }
    }
    __syncthreads();

    // Gp partial over this 128-row chunk (global writes visible post-sync)
    int c = threadIdx.x;
    const __half* qb = q + (size_t)row0 * ADIMD;
    float s = 0.f;
#pragma unroll 4
    for (int n = 0; n < 128; n++)
        s += a_sh[n] * __half2float(qb[(size_t)n * ADIMD + c]);
    Gp[(size_t)blockIdx.x * ADIMD + c] = s;
}

// ---- gsum2 with fused a-norm: G[b,c] = Σch Gp / max(||a_b||,eps) ----------
__global__ void gsum2_kernel(const float* __restrict__ Gp,
                             const float* __restrict__ a,
                             float* __restrict__ G) {
    int b = blockIdx.x;
    int c = threadIdx.x;
    float s = 0.f;
    for (int n = c; n < NTOK; n += 256) {
        float v = a[b * NTOK + n];
        s += v * v;
    }
    __shared__ float sh[8];
    s = warpSum(s);
    int w = c >> 5, l = c & 31;
    if (l == 0) sh[w] = s;
    __syncthreads();
    __shared__ float rn_sh;
    if (w == 0) {
        float v = (l < 8) ? sh[l] : 0.f;
        v = warpSum(v);
        if (l == 0) rn_sh = 1.0f / fmaxf(sqrtf(v), 1e-12f);
    }
    __syncthreads();
    float g = 0.f;
#pragma unroll
    for (int ch = 0; ch < 32; ch++)
        g += Gp[((size_t)b * 32 + ch) * ADIMD + c];
    G[b * ADIMD + c] = g * rn_sh;
}

// ---- k: l2norm + G scaling fused (one warp per row) ----------------------
__global__ void rnk_scale_kernel(__half* __restrict__ k, const float* __restrict__ G) {
    int row  = blockIdx.x * 8 + (threadIdx.x >> 5);
    int lane = threadIdx.x & 31;
    int b = row >> 12;                       // 4096 tokens per batch
    float4* r = (float4*)(k + (size_t)row * ADIMD);
    float4 v = r[lane];
    __half2* h2 = (__half2*)&v;
    float2 f[4];
    float s = 0.f;
#pragma unroll
    for (int i = 0; i < 4; i++) {
        f[i] = __half22float2(h2[i]);
        s += f[i].x * f[i].x + f[i].y * f[i].y;
    }
    s = warpSum(s);
    float inv = 1.0f / fmaxf(sqrtf(s), 1e-12f);
    const float4* G4 = (const float4*)(G + b * ADIMD);
    float4 g0 = G4[lane * 2], g1 = G4[lane * 2 + 1];
    h2[0] = __floats2half2_rn(f[0].x * inv * g0.x, f[0].y * inv * g0.y);
    h2[1] = __floats2half2_rn(f[1].x * inv * g0.z, f[1].y * inv * g0.w);
    h2[2] = __floats2half2_rn(f[2].x * inv * g1.x, f[2].y * inv * g1.y);
    h2[3] = __floats2half2_rn(f[3].x * inv * g1.z, f[3].y * inv * g1.w);
    r[lane] = v;
}

// ---------------- host orchestration --------------------------------------
extern "C" void kernel_launch(void* const* d_in, const int* in_sizes, int n_in,
                              void* d_out, int out_size) {
    const float* x_in  = (const float*)d_in[0];
    const float* ln1_g = (const float*)d_in[1];
    const float* ln1_b = (const float*)d_in[2];
    const float* Wq    = (const float*)d_in[3];
    const float* bq    = (const float*)d_in[4];
    const float* Wk    = (const float*)d_in[5];
    const float* bk    = (const float*)d_in[6];
    const float* w_g   = (const float*)d_in[7];
    const float* Wp    = (const float*)d_in[8];
    const float* bp    = (const float*)d_in[9];
    const float* Wf    = (const float*)d_in[10];
    const float* bf    = (const float*)d_in[11];
    const float* ln2_g = (const float*)d_in[12];
    const float* ln2_b = (const float*)d_in[13];
    const float* W1    = (const float*)d_in[14];
    const float* b1    = (const float*)d_in[15];
    const float* W2    = (const float*)d_in[16];
    const float* b2    = (const float*)d_in[17];

    float* x = (float*)d_out;

    void* p;
    cudaGetSymbolAddress(&p, g_h);   __half* h   = (__half*)p;
    cudaGetSymbolAddress(&p, g_q);   __half* q   = (__half*)p;
    cudaGetSymbolAddress(&p, g_k);   __half* k   = (__half*)p;
    cudaGetSymbolAddress(&p, g_att); __half* att = (__half*)p;
    cudaGetSymbolAddress(&p, g_hid); __half* hid = (__half*)p;
    cudaGetSymbolAddress(&p, g_a);   float* a    = (float*)p;
    cudaGetSymbolAddress(&p, g_G);   float* G    = (float*)p;
    cudaGetSymbolAddress(&p, g_Gp);  float* Gp   = (float*)p;
    cudaGetSymbolAddress(&p, g_Wqt); __half* Wqt = (__half*)p;
    cudaGetSymbolAddress(&p, g_Wkt); __half* Wkt = (__half*)p;
    cudaGetSymbolAddress(&p, g_Wpt); __half* Wpt = (__half*)p;
    cudaGetSymbolAddress(&p, g_Wft); __half* Wft = (__half*)p;
    cudaGetSymbolAddress(&p, g_W1t); __half* W1t = (__half*)p;
    cudaGetSymbolAddress(&p, g_W2t); __half* W2t = (__half*)p;

    cudaFuncSetAttribute(hgemm<0>, cudaFuncAttributeMaxDynamicSharedMemorySize, SMEM_HGEMM);
    cudaFuncSetAttribute(hgemm<1>, cudaFuncAttributeMaxDynamicSharedMemorySize, SMEM_HGEMM);
    cudaFuncSetAttribute(hgemm<2>, cudaFuncAttributeMaxDynamicSharedMemorySize, SMEM_HGEMM);
    cudaFuncSetAttribute(hgemm<3>, cudaFuncAttributeMaxDynamicSharedMemorySize, SMEM_HGEMM);

    cudaMemcpyAsync(x, x_in, sizeof(float) * (size_t)MROWS * DIMD,
                    cudaMemcpyDeviceToDevice);

    transpose_all<<<TRANS_BLOCKS, dim3(32, 8)>>>(Wq, Wk, Wp, Wf, W1, W2,
                                                 Wqt, Wkt, Wpt, Wft, W1t, W2t);

    const dim3 gQK (ADIMD / 128, MROWS / 128);   // (2, 128)
    const dim3 gDIM(DIMD  / 128, MROWS / 128);   // (8, 128)
    const dim3 gHID(HIDD  / 128, MROWS / 128);   // (32, 128)

    for (int i = 0; i < DEPTH; i++) {
        const __half* Wqt_i = Wqt + (size_t)i * ADIMD * DIMD;
        const __half* Wkt_i = Wkt + (size_t)i * ADIMD * DIMD;
        const __half* Wpt_i = Wpt + (size_t)i * ADIMD * ADIMD;
        const __half* Wft_i = Wft + (size_t)i * DIMD * ADIMD;
        const __half* W1t_i = W1t + (size_t)i * HIDD * DIMD;
        const __half* W2t_i = W2t + (size_t)i * DIMD * HIDD;

        ln_kernel<<<MROWS, 256>>>(x, ln1_g + i * DIMD, ln1_b + i * DIMD, h);
        hgemm<0><<<gQK, 256, SMEM_HGEMM>>>(ADIMD, DIMD, h, Wqt_i, bq + i * ADIMD, nullptr, q);
        rnq_gsum_kernel<<<MROWS / 128, 256>>>(q, w_g + i * ADIMD, a, Gp);
        gsum2_kernel<<<NB, 256>>>(Gp, a, G);
        hgemm<0><<<gQK, 256, SMEM_HGEMM>>>(ADIMD, DIMD, h, Wkt_i, bk + i * ADIMD, nullptr, k);
        rnk_scale_kernel<<<MROWS / 8, 256>>>(k, G);
        hgemm<3><<<gQK, 256, SMEM_HGEMM>>>(ADIMD, ADIMD, k, Wpt_i, bp + i * ADIMD, q, att);
        hgemm<1><<<gDIM, 256, SMEM_HGEMM>>>(DIMD, ADIMD, att, Wft_i, bf + i * DIMD, nullptr, x);
        ln_kernel<<<MROWS, 256>>>(x, ln2_g + i * DIMD, ln2_b + i * DIMD, h);
        hgemm<2><<<gHID, 256, SMEM_HGEMM>>>(HIDD, DIMD, h, W1t_i, b1 + i * HIDD, nullptr, hid);
        hgemm<1><<<gDIM, 256, SMEM_HGEMM>>>(DIMD, HIDD, hid, W2t_i, b2 + i * DIMD, nullptr, x);
    }
}

// round 10
// speedup vs baseline: 1.3021x; 1.0170x over previous
#include <cuda_runtime.h>
#include <cuda_fp16.h>
#include <math.h>
#include <stdint.h>

#define DIMD  1024
#define ADIMD 256
#define HIDD  4096
#define NTOK  4096
#define NB    4
#define MROWS (NB * NTOK)        // 16384
#define DEPTH 4
#define SCALE_A 0.25f

// ---------------- scratch (device globals) ----------------
__device__ __half g_h   [(size_t)MROWS * DIMD];
__device__ __half g_qk  [(size_t)MROWS * 512];      // q = cols [0,256), k = [256,512)
__device__ __half g_att [(size_t)MROWS * ADIMD];
__device__ __half g_hid [(size_t)MROWS * HIDD];
__device__ float  g_a   [MROWS];
__device__ float  g_G   [NB * ADIMD];
__device__ float  g_Gp  [256 * ADIMD];
__device__ float  g_bqk [DEPTH * 512];
__device__ __half g_Wqkt[(size_t)DEPTH * 512 * DIMD];   // [Wq|Wk] transposed
__device__ __half g_Wpt [(size_t)DEPTH * ADIMD * ADIMD];
__device__ __half g_Wft [(size_t)DEPTH * DIMD * ADIMD];
__device__ __half g_W1t [(size_t)DEPTH * HIDD * DIMD];
__device__ __half g_W2t [(size_t)DEPTH * DIMD * HIDD];

// ---------------- helpers ----------------
__device__ __forceinline__ float warpSum(float v) {
#pragma unroll
    for (int o = 16; o > 0; o >>= 1) v += __shfl_xor_sync(0xFFFFFFFFu, v, o);
    return v;
}
__device__ __forceinline__ uint32_t smem_u32(const void* p) {
    uint32_t a;
    asm("{ .reg .u64 t; cvta.to.shared.u64 t, %1; cvt.u32.u64 %0, t; }" : "=r"(a) : "l"(p));
    return a;
}
__device__ __forceinline__ void cp_async16(uint32_t saddr, const void* g) {
    asm volatile("cp.async.cg.shared.global [%0], [%1], 16;" :: "r"(saddr), "l"(g));
}
__device__ __forceinline__ void cp_commit() { asm volatile("cp.async.commit_group;"); }
template <int N> __device__ __forceinline__ void cp_wait() {
    asm volatile("cp.async.wait_group %0;" :: "n"(N));
}
__device__ __forceinline__ void ldsm4(uint32_t& r0, uint32_t& r1, uint32_t& r2, uint32_t& r3,
                                      uint32_t addr) {
    asm volatile("ldmatrix.sync.aligned.m8n8.x4.shared.b16 {%0,%1,%2,%3}, [%4];"
                 : "=r"(r0), "=r"(r1), "=r"(r2), "=r"(r3) : "r"(addr));
}
__device__ __forceinline__ void mma_f16(float& c0, float& c1, float& c2, float& c3,
                                        uint32_t a0, uint32_t a1, uint32_t a2, uint32_t a3,
                                        uint32_t b0, uint32_t b1) {
    asm volatile(
        "mma.sync.aligned.m16n8k16.row.col.f32.f16.f16.f32 "
        "{%0,%1,%2,%3}, {%4,%5,%6,%7}, {%8,%9}, {%0,%1,%2,%3};"
        : "+f"(c0), "+f"(c1), "+f"(c2), "+f"(c3)
        : "r"(a0), "r"(a1), "r"(a2), "r"(a3), "r"(b0), "r"(b1));
}

// ======= fp16 pipelined GEMM: CTA 128x128x32, warps 2x4 of 64x32, 4 stages =
#define A_BYTES     10240
#define STAGE_BYTES 20480
#define NSTAGE      4
#define SMEM_HGEMM  (NSTAGE * STAGE_BYTES)  // 81920

// EPI: 0 = half(AB+bias) | 1 = Cf32 += AB+bias | 2 = half(gelu(AB+bias))
//      3 = half(AB+bias+D)
// lda = A row stride (elements); ldd = D row stride (EPI 3). C row stride = N.
template <int EPI>
__global__ __launch_bounds__(256, 2)
void hgemm(int N, int K, int lda, int ldd,
           const __half* __restrict__ A,
           const __half* __restrict__ Bt,
           const float* __restrict__ bias,
           const __half* __restrict__ Dadd,
           void* __restrict__ Cv) {
    extern __shared__ char smraw[];
    const uint32_t sbase = smem_u32(smraw);

    const int bx = blockIdx.x, by = blockIdx.y;
    const int tid = threadIdx.x;
    const int lane = tid & 31;
    const int warp = tid >> 5;
    const int warpM = warp & 1;
    const int warpN = warp >> 1;
    const int tg  = lane & 3;

    const __half* Ab = A  + (size_t)by * 128 * lda;
    const __half* Bb = Bt + (size_t)bx * 128 * K;

    const uint32_t a_lane = (uint32_t)((warpM * 64 + (lane & 15)) * 80 + (lane >> 4) * 16);
    const uint32_t b_lane = (uint32_t)(A_BYTES +
        (warpN * 32 + (lane & 7) + 8 * (lane >> 4)) * 80 + ((lane >> 3) & 1) * 16);

    float acc[4][4][4];
#pragma unroll
    for (int mi = 0; mi < 4; mi++)
#pragma unroll
        for (int ni = 0; ni < 4; ni++)
#pragma unroll
            for (int r = 0; r < 4; r++) acc[mi][ni][r] = 0.f;

    const int T = K / 32;

#define LOAD_TILE(t_, s_) do {                                                  \
        uint32_t _sa = sbase + (s_) * STAGE_BYTES;                              \
        uint32_t _sb = _sa + A_BYTES;                                           \
        const __half* _ga = Ab + (size_t)(t_) * 32;                            \
        const __half* _gb = Bb + (size_t)(t_) * 32;                            \
        _Pragma("unroll")                                                       \
        for (int _i = 0; _i < 2; _i++) {                                        \
            int _id = tid + _i * 256;                                           \
            int _r = _id >> 2, _c = _id & 3;                                    \
            cp_async16(_sa + _r * 80 + _c * 16, _ga + (size_t)_r * lda + _c * 8); \
            cp_async16(_sb + _r * 80 + _c * 16, _gb + (size_t)_r * K + _c * 8);   \
        }                                                                       \
        cp_commit();                                                            \
    } while (0)

    LOAD_TILE(0, 0);
    if (T > 1) LOAD_TILE(1, 1); else cp_commit();
    if (T > 2) LOAD_TILE(2, 2); else cp_commit();

    for (int t = 0; t < T; t++) {
        cp_wait<2>();
        __syncthreads();
        if (t + 3 < T) LOAD_TILE(t + 3, (t + 3) % NSTAGE);
        else cp_commit();

        const uint32_t st = sbase + (t % NSTAGE) * STAGE_BYTES;
        const uint32_t a0addr = st + a_lane;
        const uint32_t b0addr = st + b_lane;
#pragma unroll
        for (int ks = 0; ks < 2; ks++) {
            uint32_t af[4][4], bfr[4][2];
#pragma unroll
            for (int mi = 0; mi < 4; mi++)
                ldsm4(af[mi][0], af[mi][1], af[mi][2], af[mi][3],
                      a0addr + mi * 1280 + ks * 32);
#pragma unroll
            for (int p = 0; p < 2; p++)
                ldsm4(bfr[2 * p][0], bfr[2 * p][1], bfr[2 * p + 1][0], bfr[2 * p + 1][1],
                      b0addr + p * 1280 + ks * 32);
#pragma unroll
            for (int mi = 0; mi < 4; mi++)
#pragma unroll
                for (int ni = 0; ni < 4; ni++)
                    mma_f16(acc[mi][ni][0], acc[mi][ni][1],
                            acc[mi][ni][2], acc[mi][ni][3],
                            af[mi][0], af[mi][1], af[mi][2], af[mi][3],
                            bfr[ni][0], bfr[ni][1]);
        }
    }

    const int grp8 = lane >> 2;
#pragma unroll
    for (int mi = 0; mi < 4; mi++) {
#pragma unroll
        for (int ni = 0; ni < 4; ni++) {
            int col = bx * 128 + warpN * 32 + ni * 8 + 2 * tg;
            int row0 = by * 128 + warpM * 64 + mi * 16 + grp8;
            float bv0 = bias[col], bv1 = bias[col + 1];
#pragma unroll
            for (int hh = 0; hh < 2; hh++) {
                int row = row0 + hh * 8;
                float v0 = acc[mi][ni][hh * 2 + 0] + bv0;
                float v1 = acc[mi][ni][hh * 2 + 1] + bv1;
                if (EPI == 1) {
                    float* Cp = (float*)Cv + (size_t)row * N + col;
                    float2 old = *(const float2*)Cp;
                    *(float2*)Cp = make_float2(v0 + old.x, v1 + old.y);
                } else {
                    __half* Cp = (__half*)Cv + (size_t)row * N + col;
                    if (EPI == 2) {
                        v0 = 0.5f * v0 * (1.0f + erff(v0 * 0.70710678118654752f));
                        v1 = 0.5f * v1 * (1.0f + erff(v1 * 0.70710678118654752f));
                    }
                    if (EPI == 3) {
                        float2 dv = __half22float2(
                            *(const __half2*)(Dadd + (size_t)row * ldd + col));
                        v0 += dv.x; v1 += dv.y;
                    }
                    *(__half2*)Cp = __floats2half2_rn(v0, v1);
                }
            }
        }
    }
}

// -------- single-launch transpose of ALL weights ---------------------------
// Wq/Wk interleave into Wqkt [layer][512][1024] (Wq rows 0-255, Wk rows 256-511)
#define TRANS_BLOCKS 36096
__global__ void transpose_all(const float* __restrict__ Wq, const float* __restrict__ Wk,
                              const float* __restrict__ Wp, const float* __restrict__ Wf,
                              const float* __restrict__ W1, const float* __restrict__ W2,
                              __half* __restrict__ Wqkt,
                              __half* __restrict__ Wpt, __half* __restrict__ Wft,
                              __half* __restrict__ W1t, __half* __restrict__ W2t) {
    int id = blockIdx.x;
    const float* W; __half* Wt; int K, N, base, orow;
    size_t ostride;
    if      (id < 1024)  { W = Wq; Wt = Wqkt; K = DIMD;  N = ADIMD; base = 0;
                           ostride = (size_t)512 * DIMD; orow = 0; }
    else if (id < 2048)  { W = Wk; Wt = Wqkt; K = DIMD;  N = ADIMD; base = 1024;
                           ostride = (size_t)512 * DIMD; orow = 256; }
    else if (id < 2304)  { W = Wp; Wt = Wpt;  K = ADIMD; N = ADIMD; base = 2048;
                           ostride = (size_t)K * N; orow = 0; }
    else if (id < 3328)  { W = Wf; Wt = Wft;  K = ADIMD; N = DIMD;  base = 2304;
                           ostride = (size_t)K * N; orow = 0; }
    else if (id < 19712) { W = W1; Wt = W1t;  K = DIMD;  N = HIDD;  base = 3328;
                           ostride = (size_t)K * N; orow = 0; }
    else                 { W = W2; Wt = W2t;  K = HIDD;  N = DIMD;  base = 19712;
                           ostride = (size_t)K * N; orow = 0; }
    int lid = id - base;
    int ntN = N >> 5;
    int tpl = (K >> 5) * ntN;
    int layer = lid / tpl;
    int rem   = lid % tpl;
    int n0 = (rem % ntN) * 32, k0 = (rem / ntN) * 32;
    size_t ioff = (size_t)layer * K * N;
    size_t ooff = (size_t)layer * ostride;

    __shared__ float t[32][33];
    int tx = threadIdx.x, ty = threadIdx.y;   // 32 x 8
#pragma unroll
    for (int i = 0; i < 4; i++)
        t[ty + 8 * i][tx] = W[ioff + (size_t)(k0 + ty + 8 * i) * N + n0 + tx];
    __syncthreads();
#pragma unroll
    for (int i = 0; i < 4; i++)
        Wt[ooff + (size_t)(orow + n0 + ty + 8 * i) * K + k0 + tx] =
            __float2half(t[tx][ty + 8 * i]);
}

// -------- pack [bq|bk] per layer -------------------------------------------
__global__ void pack_bias(const float* __restrict__ bq, const float* __restrict__ bk,
                          float* __restrict__ bqk) {
    int l = blockIdx.x, j = threadIdx.x;        // 512 threads
    bqk[l * 512 + j] = (j < 256) ? bq[l * 256 + j] : bk[l * 256 + j - 256];
}

// ---------------- LayerNorm: one warp per row (no block barriers) ----------
__global__ void ln_kernel(const float* __restrict__ x,
                          const float* __restrict__ g,
                          const float* __restrict__ b,
                          __half* __restrict__ out) {
    int row  = blockIdx.x * 8 + (threadIdx.x >> 5);
    int lane = threadIdx.x & 31;
    const float4* xr = (const float4*)(x + (size_t)row * DIMD);
    float4 v[8];
    float s = 0.f, s2 = 0.f;
#pragma unroll
    for (int j = 0; j < 8; j++) {
        v[j] = xr[lane + j * 32];
        s  += v[j].x + v[j].y + v[j].z + v[j].w;
        s2 += v[j].x*v[j].x + v[j].y*v[j].y + v[j].z*v[j].z + v[j].w*v[j].w;
    }
    s = warpSum(s); s2 = warpSum(s2);
    float mu  = s * (1.f / DIMD);
    float var = s2 * (1.f / DIMD) - mu * mu;
    float rs  = rsqrtf(var + 1e-6f);
    const float4* g4 = (const float4*)g;
    const float4* b4 = (const float4*)b;
    uint2* o = (uint2*)(out + (size_t)row * DIMD);
#pragma unroll
    for (int j = 0; j < 8; j++) {
        int c4 = lane + j * 32;
        float4 gg = g4[c4], bb = b4[c4];
        float o0 = (v[j].x - mu) * rs * gg.x + bb.x;
        float o1 = (v[j].y - mu) * rs * gg.y + bb.y;
        float o2 = (v[j].z - mu) * rs * gg.z + bb.z;
        float o3 = (v[j].w - mu) * rs * gg.w + bb.w;
        __half2 h0 = __floats2half2_rn(o0, o1);
        __half2 h1 = __floats2half2_rn(o2, o3);
        uint2 u;
        u.x = *(uint32_t*)&h0; u.y = *(uint32_t*)&h1;
        o[c4] = u;
    }
}

// ---- fused q pipeline: l2norm rows + a=SCALE*dot(qn,wg) + Gp partial -----
// block = 256 threads, 64 rows of the q half (stride 512). grid = 256.
__global__ void rnq_gsum_kernel(__half* __restrict__ qk,
                                const float* __restrict__ wg,
                                float* __restrict__ a_out,
                                float* __restrict__ Gp) {
    __shared__ float a_sh[64];
    const int warp = threadIdx.x >> 5, lane = threadIdx.x & 31;
    const int row0 = blockIdx.x * 64;
    const float4* w4 = (const float4*)wg;
    const float4 w0 = w4[lane * 2], w1 = w4[lane * 2 + 1];

#pragma unroll 2
    for (int i = 0; i < 8; i++) {
        int r = warp * 8 + i;
        int row = row0 + r;
        float4* rp = (float4*)(qk + (size_t)row * 512);
        float4 v = rp[lane];
        __half2* h2 = (__half2*)&v;
        float2 f[4];
        float s = 0.f;
#pragma unroll
        for (int j = 0; j < 4; j++) {
            f[j] = __half22float2(h2[j]);
            s += f[j].x * f[j].x + f[j].y * f[j].y;
        }
        s = warpSum(s);
        float inv = 1.0f / fmaxf(sqrtf(s), 1e-12f);
#pragma unroll
        for (int j = 0; j < 4; j++) {
            f[j].x *= inv; f[j].y *= inv;
            h2[j] = __floats2half2_rn(f[j].x, f[j].y);
        }
        float d = f[0].x * w0.x + f[0].y * w0.y + f[1].x * w0.z + f[1].y * w0.w
                + f[2].x * w1.x + f[2].y * w1.y + f[3].x * w1.z + f[3].y * w1.w;
        d = warpSum(d);
        rp[lane] = v;
        if (lane == 0) {
            float av = d * SCALE_A;
            a_sh[r] = av;
            a_out[row] = av;
        }
    }
    __syncthreads();

    int c = threadIdx.x;
    const __half* qb = qk + (size_t)row0 * 512;
    float s = 0.f;
#pragma unroll 4
    for (int n = 0; n < 64; n++)
        s += a_sh[n] * __half2float(qb[(size_t)n * 512 + c]);
    Gp[(size_t)blockIdx.x * ADIMD + c] = s;
}

// ---- gsum2 with fused a-norm: G[b,c] = Σch Gp / max(||a_b||,eps) ----------
__global__ void gsum2_kernel(const float* __restrict__ Gp,
                             const float* __restrict__ a,
                             float* __restrict__ G) {
    int b = blockIdx.x;
    int c = threadIdx.x;
    float s = 0.f;
    for (int n = c; n < NTOK; n += 256) {
        float v = a[b * NTOK + n];
        s += v * v;
    }
    __shared__ float sh[8];
    s = warpSum(s);
    int w = c >> 5, l = c & 31;
    if (l == 0) sh[w] = s;
    __syncthreads();
    __shared__ float rn_sh;
    if (w == 0) {
        float v = (l < 8) ? sh[l] : 0.f;
        v = warpSum(v);
        if (l == 0) rn_sh = 1.0f / fmaxf(sqrtf(v), 1e-12f);
    }
    __syncthreads();
    float g = 0.f;
#pragma unroll
    for (int ch = 0; ch < 64; ch++)
        g += Gp[((size_t)b * 64 + ch) * ADIMD + c];
    G[b * ADIMD + c] = g * rn_sh;
}

// ---- k: l2norm + G scaling fused (one warp per row, k half of qk) --------
__global__ void rnk_scale_kernel(__half* __restrict__ qk, const float* __restrict__ G) {
    int row  = blockIdx.x * 8 + (threadIdx.x >> 5);
    int lane = threadIdx.x & 31;
    int b = row >> 12;
    float4* r = (float4*)(qk + (size_t)row * 512 + 256);
    float4 v = r[lane];
    __half2* h2 = (__half2*)&v;
    float2 f[4];
    float s = 0.f;
#pragma unroll
    for (int i = 0; i < 4; i++) {
        f[i] = __half22float2(h2[i]);
        s += f[i].x * f[i].x + f[i].y * f[i].y;
    }
    s = warpSum(s);
    float inv = 1.0f / fmaxf(sqrtf(s), 1e-12f);
    const float4* G4 = (const float4*)(G + b * ADIMD);
    float4 g0 = G4[lane * 2], g1 = G4[lane * 2 + 1];
    h2[0] = __floats2half2_rn(f[0].x * inv * g0.x, f[0].y * inv * g0.y);
    h2[1] = __floats2half2_rn(f[1].x * inv * g0.z, f[1].y * inv * g0.w);
    h2[2] = __floats2half2_rn(f[2].x * inv * g1.x, f[2].y * inv * g1.y);
    h2[3] = __floats2half2_rn(f[3].x * inv * g1.z, f[3].y * inv * g1.w);
    r[lane] = v;
}

// ---------------- host orchestration --------------------------------------
extern "C" void kernel_launch(void* const* d_in, const int* in_sizes, int n_in,
                              void* d_out, int out_size) {
    const float* x_in  = (const float*)d_in[0];
    const float* ln1_g = (const float*)d_in[1];
    const float* ln1_b = (const float*)d_in[2];
    const float* Wq    = (const float*)d_in[3];
    const float* bq    = (const float*)d_in[4];
    const float* Wk    = (const float*)d_in[5];
    const float* bk    = (const float*)d_in[6];
    const float* w_g   = (const float*)d_in[7];
    const float* Wp    = (const float*)d_in[8];
    const float* bp    = (const float*)d_in[9];
    const float* Wf    = (const float*)d_in[10];
    const float* bf    = (const float*)d_in[11];
    const float* ln2_g = (const float*)d_in[12];
    const float* ln2_b = (const float*)d_in[13];
    const float* W1    = (const float*)d_in[14];
    const float* b1    = (const float*)d_in[15];
    const float* W2    = (const float*)d_in[16];
    const float* b2    = (const float*)d_in[17];

    float* x = (float*)d_out;

    void* p;
    cudaGetSymbolAddress(&p, g_h);    __half* h    = (__half*)p;
    cudaGetSymbolAddress(&p, g_qk);   __half* qk   = (__half*)p;
    cudaGetSymbolAddress(&p, g_att);  __half* att  = (__half*)p;
    cudaGetSymbolAddress(&p, g_hid);  __half* hid  = (__half*)p;
    cudaGetSymbolAddress(&p, g_a);    float* a     = (float*)p;
    cudaGetSymbolAddress(&p, g_G);    float* G     = (float*)p;
    cudaGetSymbolAddress(&p, g_Gp);   float* Gp    = (float*)p;
    cudaGetSymbolAddress(&p, g_bqk);  float* bqk   = (float*)p;
    cudaGetSymbolAddress(&p, g_Wqkt); __half* Wqkt = (__half*)p;
    cudaGetSymbolAddress(&p, g_Wpt);  __half* Wpt  = (__half*)p;
    cudaGetSymbolAddress(&p, g_Wft);  __half* Wft  = (__half*)p;
    cudaGetSymbolAddress(&p, g_W1t);  __half* W1t  = (__half*)p;
    cudaGetSymbolAddress(&p, g_W2t);  __half* W2t  = (__half*)p;

    cudaFuncSetAttribute(hgemm<0>, cudaFuncAttributeMaxDynamicSharedMemorySize, SMEM_HGEMM);
    cudaFuncSetAttribute(hgemm<1>, cudaFuncAttributeMaxDynamicSharedMemorySize, SMEM_HGEMM);
    cudaFuncSetAttribute(hgemm<2>, cudaFuncAttributeMaxDynamicSharedMemorySize, SMEM_HGEMM);
    cudaFuncSetAttribute(hgemm<3>, cudaFuncAttributeMaxDynamicSharedMemorySize, SMEM_HGEMM);

    cudaMemcpyAsync(x, x_in, sizeof(float) * (size_t)MROWS * DIMD,
                    cudaMemcpyDeviceToDevice);

    transpose_all<<<TRANS_BLOCKS, dim3(32, 8)>>>(Wq, Wk, Wp, Wf, W1, W2,
                                                 Wqkt, Wpt, Wft, W1t, W2t);
    pack_bias<<<DEPTH, 512>>>(bq, bk, bqk);

    const dim3 gQK2(512  / 128, MROWS / 128);   // (4, 128) fused q|k
    const dim3 gP  (ADIMD / 128, MROWS / 128);  // (2, 128)
    const dim3 gDIM(DIMD  / 128, MROWS / 128);  // (8, 128)
    const dim3 gHID(HIDD  / 128, MROWS / 128);  // (32, 128)

    for (int i = 0; i < DEPTH; i++) {
        const __half* Wqkt_i = Wqkt + (size_t)i * 512 * DIMD;
        const __half* Wpt_i  = Wpt  + (size_t)i * ADIMD * ADIMD;
        const __half* Wft_i  = Wft  + (size_t)i * DIMD * ADIMD;
        const __half* W1t_i  = W1t  + (size_t)i * HIDD * DIMD;
        const __half* W2t_i  = W2t  + (size_t)i * DIMD * HIDD;

        ln_kernel<<<MROWS / 8, 256>>>(x, ln1_g + i * DIMD, ln1_b + i * DIMD, h);
        // qk = h @ [Wq|Wk] + [bq|bk]
        hgemm<0><<<gQK2, 256, SMEM_HGEMM>>>(512, DIMD, DIMD, 0,
                                            h, Wqkt_i, bqk + i * 512, nullptr, qk);
        rnq_gsum_kernel<<<MROWS / 64, 256>>>(qk, w_g + i * ADIMD, a, Gp);
        gsum2_kernel<<<NB, 256>>>(Gp, a, G);
        rnk_scale_kernel<<<MROWS / 8, 256>>>(qk, G);
        // att = (G*k) @ Wp + bp + q
        hgemm<3><<<gP, 256, SMEM_HGEMM>>>(ADIMD, ADIMD, 512, 512,
                                          qk + 256, Wpt_i, bp + i * ADIMD, qk, att);
        // x += att @ Wf + bf
        hgemm<1><<<gDIM, 256, SMEM_HGEMM>>>(DIMD, ADIMD, ADIMD, 0,
                                            att, Wft_i, bf + i * DIMD, nullptr, x);
        ln_kernel<<<MROWS / 8, 256>>>(x, ln2_g + i * DIMD, ln2_b + i * DIMD, h);
        // hid = gelu(h @ W1 + b1)
        hgemm<2><<<gHID, 256, SMEM_HGEMM>>>(HIDD, DIMD, DIMD, 0,
                                            h, W1t_i, b1 + i * HIDD, nullptr, hid);
        // x += hid @ W2 + b2
        hgemm<1><<<gDIM, 256, SMEM_HGEMM>>>(DIMD, HIDD, HIDD, 0,
                                            hid, W2t_i, b2 + i * DIMD, nullptr, x);
    }
}